// round 1
// baseline (speedup 1.0000x reference)
#include <cuda_runtime.h>

#define NB 25
#define NT 40

// Scratch (static device arrays — allocation-free per harness rules)
__device__ float g_buf1[1000 * 8 * 32 * 32];   // stage A pooled spikes [bt][8][32][32]
__device__ float g_buf2[1000 * 16 * 8 * 8];    // stage B pooled spikes [bt][1024]
__device__ float g_zpart[4 * 1000 * 64];       // fc1 k-split partials [ks][bt][64]

// ---------------------------------------------------------------------------
// Stage A: conv1 (2->8, 3x3, s2, p1) + IAF over T + 2x2 avgpool, fully fused.
// grid = (16 row-tiles, 25 b), block = 256. Each thread: 1 conv-output pixel,
// all 8 out-channels; membrane state lives in registers across the t-loop.
// ---------------------------------------------------------------------------
__global__ __launch_bounds__(256) void kA(const float* __restrict__ x,
                                          const float* __restrict__ w1) {
    const int tr = blockIdx.x;   // output rows [4*tr, 4*tr+4)
    const int b  = blockIdx.y;
    const int tid = threadIdx.x;

    __shared__ float sw[144];
    __shared__ float sx[2][9][132];   // [ic][row][1+iw], idx0 = zero pad (iw=-1)
    __shared__ float spool[8][64];

    if (tid < 144) sw[tid] = w1[tid];
    if (tid < 18)  sx[tid / 9][tid % 9][0] = 0.f;
    __syncthreads();

    // weights -> registers: wr[tap][oc], tap = ic*9 + kh*3 + kw
    float wr[18][8];
#pragma unroll
    for (int ic = 0; ic < 2; ic++)
#pragma unroll
      for (int kh = 0; kh < 3; kh++)
#pragma unroll
        for (int kw = 0; kw < 3; kw++)
#pragma unroll
          for (int oc = 0; oc < 8; oc++)
            wr[ic * 9 + kh * 3 + kw][oc] = sw[((oc * 2 + ic) * 3 + kh) * 3 + kw];

    // pooling-friendly mapping: quad of lanes = one 2x2 pool cell
    const int p   = tid >> 2;            // pooled pixel 0..63 (2 rows x 32 cols)
    const int sub = tid & 3;
    const int pr  = p >> 5, pc = p & 31;
    const int ohl = 2 * pr + (sub >> 1); // local output row 0..3
    const int ow  = 2 * pc + (sub & 1);  // output col 0..63
    const int ihb = 8 * tr - 1;          // first input row of tile (may be -1)

    float v[8];
#pragma unroll
    for (int i = 0; i < 8; i++) v[i] = 0.f;

    for (int t = 0; t < NT; t++) {
        const float* xp = x + (size_t)(b * NT + t) * (2 * 128 * 128);
        __syncthreads();
        // load 2ch x 9 rows x 128 cols (float4, zero OOB rows)
        for (int i = tid; i < 576; i += 256) {
            int ch = i / 288, rem = i - ch * 288;
            int r = rem >> 5, c4 = rem & 31;
            int ih = ihb + r;
            float4 val = make_float4(0.f, 0.f, 0.f, 0.f);
            if ((unsigned)ih < 128u)
                val = *(const float4*)(xp + (ch * 128 + ih) * 128 + c4 * 4);
            float* d = &sx[ch][r][1 + c4 * 4];
            d[0] = val.x; d[1] = val.y; d[2] = val.z; d[3] = val.w;
        }
        __syncthreads();

        float acc[8];
#pragma unroll
        for (int i = 0; i < 8; i++) acc[i] = 0.f;
#pragma unroll
        for (int ic = 0; ic < 2; ic++)
#pragma unroll
          for (int kh = 0; kh < 3; kh++) {
            const float* row = &sx[ic][2 * ohl + kh][2 * ow];  // row[kw] = x[iw=2*ow-1+kw]
#pragma unroll
            for (int kw = 0; kw < 3; kw++) {
              float xv = row[kw];
#pragma unroll
              for (int oc = 0; oc < 8; oc++)
                acc[oc] = fmaf(xv, wr[ic * 9 + kh * 3 + kw][oc], acc[oc]);
            }
          }

        // IAF (integrate, single-spike, reset-to-zero, clamp -1) + 2x2 pool
#pragma unroll
        for (int oc = 0; oc < 8; oc++) {
            float vv = v[oc] + acc[oc];
            float s  = (vv >= 1.0f) ? 1.0f : 0.0f;
            vv = (s != 0.f) ? 0.f : vv;
            v[oc] = fmaxf(vv, -1.0f);
            float ps = s;
            ps += __shfl_xor_sync(0xffffffffu, ps, 1);
            ps += __shfl_xor_sync(0xffffffffu, ps, 2);
            if (sub == 0) spool[oc][p] = ps * 0.25f;
        }
        __syncthreads();

        float* outp = g_buf1 + (size_t)(b * NT + t) * 8192 + tr * 64;
        for (int i = tid; i < 512; i += 256)
            outp[(i >> 6) * 1024 + (i & 63)] = spool[i >> 6][i & 63];
    }
}

// ---------------------------------------------------------------------------
// Stage B: conv2 (8->16, 3x3, s2, p1) + IAF + 2x2 avgpool, fused.
// grid = (4 row-tiles, 2 oc-splits, 25 b), block = 128.
// Thread = (2 horizontal px, 2 oc); weights in registers (144/thread).
// Warp = one local output row -> conflict-free / broadcast input LDS.
// ---------------------------------------------------------------------------
__global__ __launch_bounds__(128) void kB(const float* __restrict__ w2) {
    const int tr = blockIdx.x;   // out rows [4*tr, 4*tr+4)
    const int os = blockIdx.y;   // oc base = 8*os
    const int b  = blockIdx.z;
    const int tid = threadIdx.x;

    __shared__ float sw[1152];
    __shared__ float sx[8][9][34];   // [ic][row][1+iw], idx0 = zero pad
    __shared__ float spB[8][4][8];   // [local oc][ohl][pc] spike pair-sums

    for (int i = tid; i < 1152; i += 128) sw[i] = w2[i];
    if (tid < 72) sx[tid / 9][tid % 9][0] = 0.f;
    __syncthreads();

    const int ohl = tid >> 5;        // warp id = local output row 0..3
    const int og  = (tid >> 3) & 3;  // oc-pair group 0..3
    const int pc  = tid & 7;         // pool col 0..7
    const int ow0 = 2 * pc;          // pair of output cols (ow0, ow0+1)
    const int oc0 = os * 8 + og * 2;

    float wrg[8][3][3][2];
#pragma unroll
    for (int ic = 0; ic < 8; ic++)
#pragma unroll
      for (int kh = 0; kh < 3; kh++)
#pragma unroll
        for (int kw = 0; kw < 3; kw++)
#pragma unroll
          for (int j = 0; j < 2; j++)
            wrg[ic][kh][kw][j] = sw[(((oc0 + j) * 8 + ic) * 3 + kh) * 3 + kw];

    float v[2][2];
    v[0][0] = v[0][1] = v[1][0] = v[1][1] = 0.f;
    const int ihb = 8 * tr - 1;

    for (int t = 0; t < NT; t++) {
        const float* inp = g_buf1 + (size_t)(b * NT + t) * 8192;
        __syncthreads();
        for (int i = tid; i < 576; i += 128) {   // 8ch x 9 rows x 8 float4
            int ch = i / 72, rem = i - ch * 72;
            int r = rem >> 3, c4 = rem & 7;
            int ih = ihb + r;
            float4 val = make_float4(0.f, 0.f, 0.f, 0.f);
            if ((unsigned)ih < 32u)
                val = *(const float4*)(inp + (ch * 32 + ih) * 32 + c4 * 4);
            float* d = &sx[ch][r][1 + c4 * 4];
            d[0] = val.x; d[1] = val.y; d[2] = val.z; d[3] = val.w;
        }
        __syncthreads();

        float acc[2][2];
        acc[0][0] = acc[0][1] = acc[1][0] = acc[1][1] = 0.f;
#pragma unroll
        for (int ic = 0; ic < 8; ic++)
#pragma unroll
          for (int kh = 0; kh < 3; kh++) {
            const float* row = &sx[ic][2 * ohl + kh][2 * ow0];
            float xr[5];
#pragma unroll
            for (int j = 0; j < 5; j++) xr[j] = row[j];
#pragma unroll
            for (int kw = 0; kw < 3; kw++)
#pragma unroll
              for (int j = 0; j < 2; j++) {
                acc[0][j] = fmaf(xr[kw],     wrg[ic][kh][kw][j], acc[0][j]);
                acc[1][j] = fmaf(xr[kw + 2], wrg[ic][kh][kw][j], acc[1][j]);
              }
          }

#pragma unroll
        for (int j = 0; j < 2; j++) {
            float sum = 0.f;
#pragma unroll
            for (int px = 0; px < 2; px++) {
                float vv = v[px][j] + acc[px][j];
                float s  = (vv >= 1.0f) ? 1.0f : 0.0f;
                vv = (s != 0.f) ? 0.f : vv;
                v[px][j] = fmaxf(vv, -1.0f);
                sum += s;
            }
            spB[og * 2 + j][ohl][pc] = sum;   // horizontal pair-sum of spikes
        }
        __syncthreads();
        // combine vertical row pairs and write pooled output (128 values/CTA)
        {
            int ocl = tid >> 4, prl = (tid >> 3) & 1, pcc = tid & 7;
            float pv = (spB[ocl][2 * prl][pcc] + spB[ocl][2 * prl + 1][pcc]) * 0.25f;
            g_buf2[(size_t)(b * NT + t) * 1024 + (os * 8 + ocl) * 64 +
                   (2 * tr + prl) * 8 + pcc] = pv;
        }
    }
}

// ---------------------------------------------------------------------------
// Stage C1: fc1 partial GEMM  z[bt,64] = buf2[bt,1024] @ w3^T, k-split x4.
// grid = (32 bt-tiles of 32 rows, 4 k-splits), block 256, thread tile 2x4.
// ---------------------------------------------------------------------------
__global__ __launch_bounds__(256) void kC1(const float* __restrict__ w3) {
    const int bt0 = blockIdx.x * 32;
    const int ks  = blockIdx.y;
    const int tid = threadIdx.x;
    __shared__ float xs[32][64];
    __shared__ float ws[64][65];
    const int rp = tid >> 4, oq = tid & 15;

    float acc[2][4];
#pragma unroll
    for (int r = 0; r < 2; r++)
#pragma unroll
      for (int j = 0; j < 4; j++) acc[r][j] = 0.f;

    for (int kc = 0; kc < 4; kc++) {
        int koff = ks * 256 + kc * 64;
        __syncthreads();
        for (int i = tid; i < 512; i += 256) {
            int r = i >> 4, c4 = i & 15;
            int bt = bt0 + r;
            float4 vv = make_float4(0.f, 0.f, 0.f, 0.f);
            if (bt < 1000) vv = *(const float4*)(g_buf2 + (size_t)bt * 1024 + koff + c4 * 4);
            *(float4*)&xs[r][c4 * 4] = vv;
        }
        for (int i = tid; i < 4096; i += 256) {   // transpose w3 chunk into smem
            int o = i >> 6, k = i & 63;
            ws[k][o] = w3[o * 1024 + koff + k];
        }
        __syncthreads();
#pragma unroll 16
        for (int k = 0; k < 64; k++) {
            float a0 = xs[2 * rp][k], a1 = xs[2 * rp + 1][k];
#pragma unroll
            for (int j = 0; j < 4; j++) {
                float wv = ws[k][oq + 16 * j];   // lanes -> consecutive banks
                acc[0][j] = fmaf(a0, wv, acc[0][j]);
                acc[1][j] = fmaf(a1, wv, acc[1][j]);
            }
        }
    }
#pragma unroll
    for (int r = 0; r < 2; r++) {
        int bt = bt0 + 2 * rp + r;
        if (bt < 1000) {
#pragma unroll
            for (int j = 0; j < 4; j++)
                g_zpart[((size_t)ks * 1000 + bt) * 64 + oq + 16 * j] = acc[r][j];
        }
    }
}

// ---------------------------------------------------------------------------
// Stage C2: sum k-split partials + IAF(64) + fc2 (64->11) + IAF(11) -> output.
// grid = 25 (b), block = 64; membrane state in registers across t.
// ---------------------------------------------------------------------------
__global__ __launch_bounds__(64) void kC2(const float* __restrict__ w4,
                                          float* __restrict__ out) {
    const int b = blockIdx.x;
    const int tid = threadIdx.x;
    __shared__ float s1[64];
    float wreg[64];
    if (tid < 11) {
#pragma unroll
        for (int j = 0; j < 64; j++) wreg[j] = w4[tid * 64 + j];
    }
    float v1 = 0.f, v2 = 0.f;
    for (int t = 0; t < NT; t++) {
        int bt = b * NT + t;
        float z = g_zpart[(0 * 1000 + bt) * 64 + tid]
                + g_zpart[(1 * 1000 + bt) * 64 + tid]
                + g_zpart[(2 * 1000 + bt) * 64 + tid]
                + g_zpart[(3 * 1000 + bt) * 64 + tid];
        float vv = v1 + z;
        float s  = (vv >= 1.0f) ? 1.0f : 0.0f;
        vv = (s != 0.f) ? 0.f : vv;
        v1 = fmaxf(vv, -1.0f);
        s1[tid] = s;
        __syncthreads();
        if (tid < 11) {
            float za = 0.f, zb = 0.f;
#pragma unroll
            for (int j = 0; j < 64; j += 2) {
                za = fmaf(s1[j],     wreg[j],     za);
                zb = fmaf(s1[j + 1], wreg[j + 1], zb);
            }
            float vv2 = v2 + (za + zb);
            float s2  = (vv2 >= 1.0f) ? 1.0f : 0.0f;
            vv2 = (s2 != 0.f) ? 0.f : vv2;
            v2 = fmaxf(vv2, -1.0f);
            out[bt * 11 + tid] = s2;
        }
        __syncthreads();
    }
}

// ---------------------------------------------------------------------------
extern "C" void kernel_launch(void* const* d_in, const int* in_sizes, int n_in,
                              void* d_out, int out_size) {
    (void)in_sizes; (void)n_in; (void)out_size;
    const float* x  = (const float*)d_in[0];
    const float* w1 = (const float*)d_in[1];
    const float* w2 = (const float*)d_in[2];
    const float* w3 = (const float*)d_in[3];
    const float* w4 = (const float*)d_in[4];
    float* out = (float*)d_out;

    kA<<<dim3(16, 25), 256>>>(x, w1);
    kB<<<dim3(4, 2, 25), 128>>>(w2);
    kC1<<<dim3(32, 4), 256>>>(w3);
    kC2<<<25, 64>>>(w4, out);
}

// round 2
// speedup vs baseline: 2.0048x; 2.0048x over previous
#include <cuda_runtime.h>

#define NB 25
#define NT 40

// Scratch (static device arrays — allocation-free per harness rules)
__device__ float g_buf1[1000 * 8 * 32 * 32];   // stage A pooled spikes [bt][8][32][32]
__device__ float g_buf2[1000 * 16 * 8 * 8];    // stage B pooled spikes [bt][1024]
__device__ float g_zpart[4 * 1000 * 64];       // fc1 k-split partials [ks][bt][64]

// ---------------------------------------------------------------------------
// Stage A: conv1 (2->8, 3x3, s2, p1) + IAF over T + 2x2 avgpool, fused.
// grid = (16 row-tiles, 25 b), block = 512.
// Thread = (pool cell, 2x2 sub-pixel, oc-half of 4). Double-buffered input.
// ---------------------------------------------------------------------------
__global__ __launch_bounds__(512) void kA(const float* __restrict__ x,
                                          const float* __restrict__ w1) {
    const int tr = blockIdx.x;   // output rows [4*tr, 4*tr+4)
    const int b  = blockIdx.y;
    const int tid = threadIdx.x;

    __shared__ float sw[144];
    __shared__ float sx[2][2][9][132];   // [buf][ic][row][1+iw], idx0 = zero pad
    __shared__ float spool[2][8][64];    // [buf][oc][pool cell]

    if (tid < 144) sw[tid] = w1[tid];
    if (tid < 36) { int bs = tid / 18, r = tid % 18; sx[bs][r / 9][r % 9][0] = 0.f; }
    __syncthreads();

    // tid bits: [0]=oc-half, [1:2]=sub(2x2), [3:8]=pool cell
    const int oh  = tid & 1;
    const int sub = (tid >> 1) & 3;
    const int p   = tid >> 3;            // pooled pixel 0..63 (2 rows x 32 cols)
    const int pr  = p >> 5, pc = p & 31;
    const int ohl = 2 * pr + (sub >> 1); // local output row 0..3
    const int ow  = 2 * pc + (sub & 1);  // output col 0..63
    const int ihb = 8 * tr - 1;          // first input row of tile (may be -1)

    // weights -> registers: 4 ocs per thread
    float wr[18][4];
#pragma unroll
    for (int ic = 0; ic < 2; ic++)
#pragma unroll
      for (int kh = 0; kh < 3; kh++)
#pragma unroll
        for (int kw = 0; kw < 3; kw++)
#pragma unroll
          for (int i = 0; i < 4; i++)
            wr[ic * 9 + kh * 3 + kw][i] = sw[((oh * 4 + i) * 2 + ic) * 9 + kh * 3 + kw];

    // precomputed load-slot indices (2ch x 9row x 32 float4 = 576 slots / 512 thr)
    const int iA = tid;
    const int chA = (iA >= 288) ? 1 : 0;
    const int remA = iA - chA * 288;
    const int rA = remA >> 5, cA = remA & 31;
    const int ihA = ihb + rA;
    const bool actB = tid < 64;
    const int remB = tid + 512 - 288;          // slot iB = tid+512 (always ch=1)
    const int rB = remB >> 5, cB = remB & 31;
    const int ihB = ihb + rB;

    float4 fA, fB;
    // prefetch t=0
    {
        const float* xp = x + (size_t)(b * NT) * 32768;
        fA = make_float4(0.f, 0.f, 0.f, 0.f);
        if ((unsigned)ihA < 128u) fA = *(const float4*)(xp + (chA * 128 + ihA) * 128 + cA * 4);
        fB = make_float4(0.f, 0.f, 0.f, 0.f);
        if (actB && (unsigned)ihB < 128u) fB = *(const float4*)(xp + (128 + ihB) * 128 + cB * 4);
    }
    { float* d = &sx[0][chA][rA][1 + cA * 4]; d[0]=fA.x; d[1]=fA.y; d[2]=fA.z; d[3]=fA.w; }
    if (actB) { float* d = &sx[0][1][rB][1 + cB * 4]; d[0]=fB.x; d[1]=fB.y; d[2]=fB.z; d[3]=fB.w; }
    __syncthreads();

    float v[4];
#pragma unroll
    for (int i = 0; i < 4; i++) v[i] = 0.f;

    for (int t = 0; t < NT; t++) {
        const int cur = t & 1;
        // prefetch t+1 into registers (overlaps with compute below)
        if (t + 1 < NT) {
            const float* xp = x + (size_t)(b * NT + t + 1) * 32768;
            fA = make_float4(0.f, 0.f, 0.f, 0.f);
            if ((unsigned)ihA < 128u) fA = *(const float4*)(xp + (chA * 128 + ihA) * 128 + cA * 4);
            fB = make_float4(0.f, 0.f, 0.f, 0.f);
            if (actB && (unsigned)ihB < 128u) fB = *(const float4*)(xp + (128 + ihB) * 128 + cB * 4);
        }

        float acc[4];
#pragma unroll
        for (int i = 0; i < 4; i++) acc[i] = 0.f;
#pragma unroll
        for (int ic = 0; ic < 2; ic++)
#pragma unroll
          for (int kh = 0; kh < 3; kh++) {
            const float* row = &sx[cur][ic][2 * ohl + kh][2 * ow];
#pragma unroll
            for (int kw = 0; kw < 3; kw++) {
              float xv = row[kw];
#pragma unroll
              for (int i = 0; i < 4; i++)
                acc[i] = fmaf(xv, wr[ic * 9 + kh * 3 + kw][i], acc[i]);
            }
          }

        // IAF + 2x2 pool via intra-warp shuffles (sub bits at lane bits 1..2)
#pragma unroll
        for (int i = 0; i < 4; i++) {
            float vv = v[i] + acc[i];
            float s  = (vv >= 1.0f) ? 1.0f : 0.0f;
            vv = (s != 0.f) ? 0.f : vv;
            v[i] = fmaxf(vv, -1.0f);
            float ps = s;
            ps += __shfl_xor_sync(0xffffffffu, ps, 2);
            ps += __shfl_xor_sync(0xffffffffu, ps, 4);
            if (sub == 0) spool[cur][oh * 4 + i][p] = ps * 0.25f;
        }

        // commit prefetched tile into the other buffer
        if (t + 1 < NT) {
            { float* d = &sx[cur ^ 1][chA][rA][1 + cA * 4]; d[0]=fA.x; d[1]=fA.y; d[2]=fA.z; d[3]=fA.w; }
            if (actB) { float* d = &sx[cur ^ 1][1][rB][1 + cB * 4]; d[0]=fB.x; d[1]=fB.y; d[2]=fB.z; d[3]=fB.w; }
        }
        __syncthreads();

        // coalesced store of pooled spikes
        float* outp = g_buf1 + (size_t)(b * NT + t) * 8192 + tr * 64;
        outp[(tid >> 6) * 1024 + (tid & 63)] = spool[cur][tid >> 6][tid & 63];
        // (512 threads cover 8 oc x 64 cells exactly once)
    }
}

// ---------------------------------------------------------------------------
// Stage B: conv2 (8->16, 3x3, s2, p1) + IAF + 2x2 avgpool, fused.
// grid = (4 row-tiles, 2 oc-splits, 25 b), block = 128. Double-buffered input.
// ---------------------------------------------------------------------------
__global__ __launch_bounds__(128) void kB(const float* __restrict__ w2) {
    const int tr = blockIdx.x;   // out rows [4*tr, 4*tr+4)
    const int os = blockIdx.y;   // oc base = 8*os
    const int b  = blockIdx.z;
    const int tid = threadIdx.x;

    __shared__ float sw[1152];
    __shared__ float sx[2][8][9][34];  // [buf][ic][row][1+iw], idx0 = zero pad
    __shared__ float spB[2][8][4][8];  // [buf][local oc][ohl][pc]

    for (int i = tid; i < 1152; i += 128) sw[i] = w2[i];
    if (tid < 72) { sx[0][tid / 9][tid % 9][0] = 0.f; sx[1][tid / 9][tid % 9][0] = 0.f; }
    __syncthreads();

    const int ohl = tid >> 5;        // warp id = local output row 0..3
    const int og  = (tid >> 3) & 3;  // oc-pair group 0..3
    const int pc  = tid & 7;         // pool col 0..7
    const int ow0 = 2 * pc;
    const int oc0 = os * 8 + og * 2;

    float wrg[8][3][3][2];
#pragma unroll
    for (int ic = 0; ic < 8; ic++)
#pragma unroll
      for (int kh = 0; kh < 3; kh++)
#pragma unroll
        for (int kw = 0; kw < 3; kw++)
#pragma unroll
          for (int j = 0; j < 2; j++)
            wrg[ic][kh][kw][j] = sw[(((oc0 + j) * 8 + ic) * 3 + kh) * 3 + kw];

    const int ihb = 8 * tr - 1;
    // load slots: 8ch x 9row x 8 float4 = 576 over 128 thr -> 4 full + 1 partial
    int lch[5], lr[5], lc[5], lih[5]; bool lact[5];
#pragma unroll
    for (int k = 0; k < 5; k++) {
        int i = tid + k * 128;
        lact[k] = (i < 576);
        int ii = lact[k] ? i : 0;
        lch[k] = ii / 72; int rem = ii - lch[k] * 72;
        lr[k] = rem >> 3; lc[k] = rem & 7; lih[k] = ihb + lr[k];
    }

    float4 f[5];
    // prefetch t=0
    {
        const float* inp = g_buf1 + (size_t)(b * NT) * 8192;
#pragma unroll
        for (int k = 0; k < 5; k++) {
            f[k] = make_float4(0.f, 0.f, 0.f, 0.f);
            if (lact[k] && (unsigned)lih[k] < 32u)
                f[k] = *(const float4*)(inp + (lch[k] * 32 + lih[k]) * 32 + lc[k] * 4);
        }
    }
#pragma unroll
    for (int k = 0; k < 5; k++) if (lact[k]) {
        float* d = &sx[0][lch[k]][lr[k]][1 + lc[k] * 4];
        d[0]=f[k].x; d[1]=f[k].y; d[2]=f[k].z; d[3]=f[k].w;
    }
    __syncthreads();

    float v[2][2];
    v[0][0] = v[0][1] = v[1][0] = v[1][1] = 0.f;

    for (int t = 0; t < NT; t++) {
        const int cur = t & 1;
        if (t + 1 < NT) {
            const float* inp = g_buf1 + (size_t)(b * NT + t + 1) * 8192;
#pragma unroll
            for (int k = 0; k < 5; k++) {
                f[k] = make_float4(0.f, 0.f, 0.f, 0.f);
                if (lact[k] && (unsigned)lih[k] < 32u)
                    f[k] = *(const float4*)(inp + (lch[k] * 32 + lih[k]) * 32 + lc[k] * 4);
            }
        }

        float acc[2][2];
        acc[0][0] = acc[0][1] = acc[1][0] = acc[1][1] = 0.f;
#pragma unroll
        for (int ic = 0; ic < 8; ic++)
#pragma unroll
          for (int kh = 0; kh < 3; kh++) {
            const float* row = &sx[cur][ic][2 * ohl + kh][2 * ow0];
            float xr[5];
#pragma unroll
            for (int j = 0; j < 5; j++) xr[j] = row[j];
#pragma unroll
            for (int kw = 0; kw < 3; kw++)
#pragma unroll
              for (int j = 0; j < 2; j++) {
                acc[0][j] = fmaf(xr[kw],     wrg[ic][kh][kw][j], acc[0][j]);
                acc[1][j] = fmaf(xr[kw + 2], wrg[ic][kh][kw][j], acc[1][j]);
              }
          }

#pragma unroll
        for (int j = 0; j < 2; j++) {
            float sum = 0.f;
#pragma unroll
            for (int px = 0; px < 2; px++) {
                float vv = v[px][j] + acc[px][j];
                float s  = (vv >= 1.0f) ? 1.0f : 0.0f;
                vv = (s != 0.f) ? 0.f : vv;
                v[px][j] = fmaxf(vv, -1.0f);
                sum += s;
            }
            spB[cur][og * 2 + j][ohl][pc] = sum;
        }

        if (t + 1 < NT) {
#pragma unroll
            for (int k = 0; k < 5; k++) if (lact[k]) {
                float* d = &sx[cur ^ 1][lch[k]][lr[k]][1 + lc[k] * 4];
                d[0]=f[k].x; d[1]=f[k].y; d[2]=f[k].z; d[3]=f[k].w;
            }
        }
        __syncthreads();

        // combine vertical row pairs, write pooled output (128 values/CTA)
        {
            int ocl = tid >> 4, prl = (tid >> 3) & 1, pcc = tid & 7;
            float pv = (spB[cur][ocl][2 * prl][pcc] + spB[cur][ocl][2 * prl + 1][pcc]) * 0.25f;
            g_buf2[(size_t)(b * NT + t) * 1024 + (os * 8 + ocl) * 64 +
                   (2 * tr + prl) * 8 + pcc] = pv;
        }
    }
}

// ---------------------------------------------------------------------------
// Stage C1: fc1 partial GEMM  z[bt,64] = buf2[bt,1024] @ w3^T, k-split x4.
// grid = (32 bt-tiles of 32 rows, 4 k-splits), block 256, thread tile 2x4.
// ---------------------------------------------------------------------------
__global__ __launch_bounds__(256) void kC1(const float* __restrict__ w3) {
    const int bt0 = blockIdx.x * 32;
    const int ks  = blockIdx.y;
    const int tid = threadIdx.x;
    __shared__ float xs[32][64];
    __shared__ float ws[64][65];
    const int rp = tid >> 4, oq = tid & 15;

    float acc[2][4];
#pragma unroll
    for (int r = 0; r < 2; r++)
#pragma unroll
      for (int j = 0; j < 4; j++) acc[r][j] = 0.f;

    for (int kc = 0; kc < 4; kc++) {
        int koff = ks * 256 + kc * 64;
        __syncthreads();
        for (int i = tid; i < 512; i += 256) {
            int r = i >> 4, c4 = i & 15;
            int bt = bt0 + r;
            float4 vv = make_float4(0.f, 0.f, 0.f, 0.f);
            if (bt < 1000) vv = *(const float4*)(g_buf2 + (size_t)bt * 1024 + koff + c4 * 4);
            *(float4*)&xs[r][c4 * 4] = vv;
        }
        for (int i = tid; i < 4096; i += 256) {   // transpose w3 chunk into smem
            int o = i >> 6, k = i & 63;
            ws[k][o] = w3[o * 1024 + koff + k];
        }
        __syncthreads();
#pragma unroll 16
        for (int k = 0; k < 64; k++) {
            float a0 = xs[2 * rp][k], a1 = xs[2 * rp + 1][k];
#pragma unroll
            for (int j = 0; j < 4; j++) {
                float wv = ws[k][oq + 16 * j];
                acc[0][j] = fmaf(a0, wv, acc[0][j]);
                acc[1][j] = fmaf(a1, wv, acc[1][j]);
            }
        }
    }
#pragma unroll
    for (int r = 0; r < 2; r++) {
        int bt = bt0 + 2 * rp + r;
        if (bt < 1000) {
#pragma unroll
            for (int j = 0; j < 4; j++)
                g_zpart[((size_t)ks * 1000 + bt) * 64 + oq + 16 * j] = acc[r][j];
        }
    }
}

// ---------------------------------------------------------------------------
// Stage C2: preload+reduce partials to smem, then IAF(64)+fc2+IAF(11) scan
// entirely out of shared memory. grid = 25 (b), block = 128.
// ---------------------------------------------------------------------------
__global__ __launch_bounds__(128) void kC2(const float* __restrict__ w4,
                                           float* __restrict__ out) {
    const int b = blockIdx.x;
    const int tid = threadIdx.x;
    __shared__ float zs[NT * 64];   // 10 KB: z[t][cell]
    __shared__ float s1[2][64];

    // parallel load + k-split reduce: 2560 floats = 640 float4
    const float* p0 = g_zpart + (size_t)b * 2560;
    for (int i = tid; i < 640; i += 128) {
        float4 a = *(const float4*)(p0 + 0 * 64000 + i * 4);
        float4 c = *(const float4*)(p0 + 1 * 64000 + i * 4);
        float4 d = *(const float4*)(p0 + 2 * 64000 + i * 4);
        float4 e = *(const float4*)(p0 + 3 * 64000 + i * 4);
        float4 r = make_float4(a.x + c.x + d.x + e.x, a.y + c.y + d.y + e.y,
                               a.z + c.z + d.z + e.z, a.w + c.w + d.w + e.w);
        *(float4*)&zs[i * 4] = r;
    }

    float wreg[64];
    if (tid < 11) {
#pragma unroll
        for (int j = 0; j < 64; j++) wreg[j] = w4[tid * 64 + j];
    }
    __syncthreads();

    float v1 = 0.f, v2 = 0.f;
    for (int t = 0; t < NT; t++) {
        if (tid < 64) {
            float vv = v1 + zs[t * 64 + tid];
            float s  = (vv >= 1.0f) ? 1.0f : 0.0f;
            vv = (s != 0.f) ? 0.f : vv;
            v1 = fmaxf(vv, -1.0f);
            s1[t & 1][tid] = s;
        }
        __syncthreads();
        if (tid < 11) {
            float za = 0.f, zb = 0.f, zc = 0.f, zd = 0.f;
            const float* sp = s1[t & 1];
#pragma unroll
            for (int j = 0; j < 64; j += 4) {
                za = fmaf(sp[j],     wreg[j],     za);
                zb = fmaf(sp[j + 1], wreg[j + 1], zb);
                zc = fmaf(sp[j + 2], wreg[j + 2], zc);
                zd = fmaf(sp[j + 3], wreg[j + 3], zd);
            }
            float vv2 = v2 + ((za + zb) + (zc + zd));
            float s2  = (vv2 >= 1.0f) ? 1.0f : 0.0f;
            vv2 = (s2 != 0.f) ? 0.f : vv2;
            v2 = fmaxf(vv2, -1.0f);
            out[(b * NT + t) * 11 + tid] = s2;
        }
    }
}

// ---------------------------------------------------------------------------
extern "C" void kernel_launch(void* const* d_in, const int* in_sizes, int n_in,
                              void* d_out, int out_size) {
    (void)in_sizes; (void)n_in; (void)out_size;
    const float* x  = (const float*)d_in[0];
    const float* w1 = (const float*)d_in[1];
    const float* w2 = (const float*)d_in[2];
    const float* w3 = (const float*)d_in[3];
    const float* w4 = (const float*)d_in[4];
    float* out = (float*)d_out;

    kA<<<dim3(16, 25), 512>>>(x, w1);
    kB<<<dim3(4, 2, 25), 128>>>(w2);
    kC1<<<dim3(32, 4), 256>>>(w3);
    kC2<<<25, 128>>>(w4, out);
}

// round 4
// speedup vs baseline: 2.3510x; 1.1727x over previous
#include <cuda_runtime.h>
#include <cstdint>

#define NB 25
#define NT 40

// Scratch (static device arrays — allocation-free per harness rules)
__device__ float g_buf1[1000 * 8 * 32 * 32];   // stage A pooled spikes [bt][8][32][32]
__device__ float g_buf2[1000 * 16 * 8 * 8];    // stage B pooled spikes [bt][1024]
__device__ float g_zpart[4 * 1000 * 64];       // fc1 k-split partials [ks][bt][64]

__device__ __forceinline__ void cp16(uint32_t dst, const void* src, int bytes) {
    asm volatile("cp.async.cg.shared.global [%0], [%1], 16, %2;\n"
                 :: "r"(dst), "l"(src), "r"(bytes));
}
__device__ __forceinline__ void cp_commit() { asm volatile("cp.async.commit_group;\n" ::); }
__device__ __forceinline__ void cp_wait2()  { asm volatile("cp.async.wait_group 2;\n" ::); }
__device__ __forceinline__ uint32_t saddr(const void* p) {
    return (uint32_t)__cvta_generic_to_shared(p);
}

// ---------------------------------------------------------------------------
// Stage A: conv1 (2->8, 3x3, s2, p1) + IAF over T + 2x2 avgpool, fused.
// grid = (16 row-tiles, 25 b), block = 512.  3-stage cp.async pipeline.
// smem row layout: data at [4+iw], zero pad at [3] (keeps cp.async dst 16B-aligned).
// ---------------------------------------------------------------------------
__global__ __launch_bounds__(512) void kA(const float* __restrict__ x,
                                          const float* __restrict__ w1) {
    const int tr = blockIdx.x;   // output rows [4*tr, 4*tr+4)
    const int b  = blockIdx.y;
    const int tid = threadIdx.x;

    __shared__ float sw[144];
    __shared__ float sx[3][2][9][132];   // [buf][ic][row][4+iw]; [3] = zero pad
    __shared__ float spool[8][64];

    if (tid < 144) sw[tid] = w1[tid];
    if (tid < 54) { int bu = tid / 18, r = tid % 18; sx[bu][r / 9][r % 9][3] = 0.f; }

    // tid bits: [0]=oc-half, [1:2]=sub(2x2), [3:8]=pool cell
    const int oh  = tid & 1;
    const int sub = (tid >> 1) & 3;
    const int p   = tid >> 3;            // pooled pixel 0..63 (2 rows x 32 cols)
    const int pr  = p >> 5, pc = p & 31;
    const int ohl = 2 * pr + (sub >> 1); // local output row 0..3
    const int ow  = 2 * pc + (sub & 1);  // output col 0..63
    const int ihb = 8 * tr - 1;          // first input row of tile (may be -1)

    // load slots: 2ch x 9row x 32 float4 = 576 slots over 512 threads
    const int chA  = (tid >= 288) ? 1 : 0;
    const int remA = tid - chA * 288;
    const int rA = remA >> 5, cA = remA & 31;
    const int ihA = ihb + rA;
    const bool actB = tid < 64;
    const int remB = tid + 224;          // slot tid+512 (always ch=1)
    const int rB = remB >> 5, cB = remB & 31;
    const int ihB = ihb + rB;

    __syncthreads();  // sw + pads visible

    float wr[18][4];
#pragma unroll
    for (int ic = 0; ic < 2; ic++)
#pragma unroll
      for (int kh = 0; kh < 3; kh++)
#pragma unroll
        for (int kw = 0; kw < 3; kw++)
#pragma unroll
          for (int i = 0; i < 4; i++)
            wr[ic * 9 + kh * 3 + kw][i] = sw[((oh * 4 + i) * 2 + ic) * 9 + kh * 3 + kw];

    auto issue = [&](int t, int bu) {
        const float* xp = x + (size_t)(b * NT + t) * 32768;
        {
            int ih = (ihA < 0) ? 0 : ihA;
            int by = ((unsigned)ihA < 128u) ? 16 : 0;
            cp16(saddr(&sx[bu][chA][rA][4 + cA * 4]),
                 xp + (chA * 128 + ih) * 128 + cA * 4, by);
        }
        if (actB) {
            int ih = (ihB < 0) ? 0 : ihB;
            int by = ((unsigned)ihB < 128u) ? 16 : 0;
            cp16(saddr(&sx[bu][1][rB][4 + cB * 4]),
                 xp + (128 + ih) * 128 + cB * 4, by);
        }
    };

    issue(0, 0); cp_commit();
    issue(1, 1); cp_commit();

    float v[4];
#pragma unroll
    for (int i = 0; i < 4; i++) v[i] = 0.f;

    for (int t = 0; t < NT; t++) {
        const int cur = t % 3;
        if (t + 2 < NT) issue(t + 2, (t + 2) % 3);
        cp_commit();                 // uniform group count every iteration
        cp_wait2();                  // tile t complete (this thread)
        __syncthreads();             // tile t visible to all

        float acc[4];
#pragma unroll
        for (int i = 0; i < 4; i++) acc[i] = 0.f;
#pragma unroll
        for (int ic = 0; ic < 2; ic++)
#pragma unroll
          for (int kh = 0; kh < 3; kh++) {
            const float* row = &sx[cur][ic][2 * ohl + kh][3 + 2 * ow];
#pragma unroll
            for (int kw = 0; kw < 3; kw++) {
              float xv = row[kw];
#pragma unroll
              for (int i = 0; i < 4; i++)
                acc[i] = fmaf(xv, wr[ic * 9 + kh * 3 + kw][i], acc[i]);
            }
          }

        // IAF + 2x2 pool via intra-warp shuffles (sub bits at lane bits 1..2)
#pragma unroll
        for (int i = 0; i < 4; i++) {
            float vv = v[i] + acc[i];
            float s  = (vv >= 1.0f) ? 1.0f : 0.0f;
            vv = (s != 0.f) ? 0.f : vv;
            v[i] = fmaxf(vv, -1.0f);
            float ps = s;
            ps += __shfl_xor_sync(0xffffffffu, ps, 2);
            ps += __shfl_xor_sync(0xffffffffu, ps, 4);
            if (sub == 0) spool[oh * 4 + i][p] = ps * 0.25f;
        }
        __syncthreads();

        // coalesced store of pooled spikes (512 threads = 8 oc x 64 cells)
        float* outp = g_buf1 + (size_t)(b * NT + t) * 8192 + tr * 64;
        outp[(tid >> 6) * 1024 + (tid & 63)] = spool[tid >> 6][tid & 63];
    }
}

// ---------------------------------------------------------------------------
// Stage B: conv2 (8->16, 3x3, s2, p1) + IAF + 2x2 avgpool, fused.
// grid = (4 row-tiles, 4 oc-splits, 25 b), block = 128. 3-stage cp.async.
// Thread = (row=warp, oc-pair, 1 output col); 4 ocs per CTA.
// ---------------------------------------------------------------------------
__global__ __launch_bounds__(128) void kB(const float* __restrict__ w2) {
    const int tr = blockIdx.x;   // out rows [4*tr, 4*tr+4)
    const int os = blockIdx.y;   // oc base = 4*os
    const int b  = blockIdx.z;
    const int tid = threadIdx.x;

    __shared__ float sw[288];
    __shared__ float sx[3][8][9][36];  // [buf][ic][row][4+iw]; [3] = zero pad
    __shared__ float spB[4][4][8];     // [local oc][ohl][pool col]

    for (int i = tid; i < 288; i += 128) sw[i] = w2[os * 288 + i];
    for (int i = tid; i < 216; i += 128) {
        int bu = i / 72, r = i % 72;
        sx[bu][r / 9][r % 9][3] = 0.f;
    }

    const int ohl = tid >> 5;        // warp = local output row 0..3
    const int oh2 = (tid >> 4) & 1;  // oc-pair 0..1
    const int ow  = tid & 15;        // output col 0..15
    const int ihb = 8 * tr - 1;

    // load slots: 8ch x 9row x 8 float4 = 576 over 128 thr -> 4 full + 1 partial
    int lch[5], lr[5], lc[5], lih[5]; bool lact[5];
#pragma unroll
    for (int k = 0; k < 5; k++) {
        int i = tid + k * 128;
        lact[k] = (i < 576);
        int ii = lact[k] ? i : 0;
        lch[k] = ii / 72; int rem = ii - lch[k] * 72;
        lr[k] = rem >> 3; lc[k] = rem & 7; lih[k] = ihb + lr[k];
    }

    __syncthreads();

    float wrg[8][3][3][2];
#pragma unroll
    for (int ic = 0; ic < 8; ic++)
#pragma unroll
      for (int kh = 0; kh < 3; kh++)
#pragma unroll
        for (int kw = 0; kw < 3; kw++)
#pragma unroll
          for (int j = 0; j < 2; j++)
            wrg[ic][kh][kw][j] = sw[(oh2 * 2 + j) * 72 + ic * 9 + kh * 3 + kw];

    auto issue = [&](int t, int bu) {
        const float* inp = g_buf1 + (size_t)(b * NT + t) * 8192;
#pragma unroll
        for (int k = 0; k < 5; k++) {
            if (!lact[k]) continue;
            int ih = (lih[k] < 0) ? 0 : lih[k];
            int by = ((unsigned)lih[k] < 32u) ? 16 : 0;
            cp16(saddr(&sx[bu][lch[k]][lr[k]][4 + lc[k] * 4]),
                 inp + (lch[k] * 32 + ih) * 32 + lc[k] * 4, by);
        }
    };

    issue(0, 0); cp_commit();
    issue(1, 1); cp_commit();

    float v[2];
    v[0] = v[1] = 0.f;

    for (int t = 0; t < NT; t++) {
        const int cur = t % 3;
        if (t + 2 < NT) issue(t + 2, (t + 2) % 3);
        cp_commit();
        cp_wait2();
        __syncthreads();

        float acc[2];
        acc[0] = acc[1] = 0.f;
#pragma unroll
        for (int ic = 0; ic < 8; ic++)
#pragma unroll
          for (int kh = 0; kh < 3; kh++) {
            const float* row = &sx[cur][ic][2 * ohl + kh][3 + 2 * ow];
#pragma unroll
            for (int kw = 0; kw < 3; kw++) {
                float xv = row[kw];
                acc[0] = fmaf(xv, wrg[ic][kh][kw][0], acc[0]);
                acc[1] = fmaf(xv, wrg[ic][kh][kw][1], acc[1]);
            }
          }

        // IAF + horizontal pool via shfl (ow bit0 = tid bit0)
        float ps[2];
#pragma unroll
        for (int j = 0; j < 2; j++) {
            float vv = v[j] + acc[j];
            float s  = (vv >= 1.0f) ? 1.0f : 0.0f;
            vv = (s != 0.f) ? 0.f : vv;
            v[j] = fmaxf(vv, -1.0f);
            ps[j] = s + __shfl_xor_sync(0xffffffffu, s, 1);
        }
        if ((ow & 1) == 0) {
            spB[oh2 * 2 + 0][ohl][ow >> 1] = ps[0];
            spB[oh2 * 2 + 1][ohl][ow >> 1] = ps[1];
        }
        __syncthreads();

        // vertical pair combine + pooled store (64 values/CTA)
        if (tid < 64) {
            int ocl = tid >> 4, prl = (tid >> 3) & 1, pcc = tid & 7;
            float pv = (spB[ocl][2 * prl][pcc] + spB[ocl][2 * prl + 1][pcc]) * 0.25f;
            g_buf2[(size_t)(b * NT + t) * 1024 + (os * 4 + ocl) * 64 +
                   (2 * tr + prl) * 8 + pcc] = pv;
        }
    }
}

// ---------------------------------------------------------------------------
// Stage C1: fc1 partial GEMM  z[bt,64] = buf2[bt,1024] @ w3^T, k-split x4.
// grid = (32 bt-tiles of 32 rows, 4 k-splits), block 256, thread tile 2x4.
// ---------------------------------------------------------------------------
__global__ __launch_bounds__(256) void kC1(const float* __restrict__ w3) {
    const int bt0 = blockIdx.x * 32;
    const int ks  = blockIdx.y;
    const int tid = threadIdx.x;
    __shared__ float xs[32][64];
    __shared__ float ws[64][65];
    const int rp = tid >> 4, oq = tid & 15;

    float acc[2][4];
#pragma unroll
    for (int r = 0; r < 2; r++)
#pragma unroll
      for (int j = 0; j < 4; j++) acc[r][j] = 0.f;

    for (int kc = 0; kc < 4; kc++) {
        int koff = ks * 256 + kc * 64;
        __syncthreads();
        for (int i = tid; i < 512; i += 256) {
            int r = i >> 4, c4 = i & 15;
            int bt = bt0 + r;
            float4 vv = make_float4(0.f, 0.f, 0.f, 0.f);
            if (bt < 1000) vv = *(const float4*)(g_buf2 + (size_t)bt * 1024 + koff + c4 * 4);
            *(float4*)&xs[r][c4 * 4] = vv;
        }
        for (int i = tid; i < 4096; i += 256) {   // transpose w3 chunk into smem
            int o = i >> 6, k = i & 63;
            ws[k][o] = w3[o * 1024 + koff + k];
        }
        __syncthreads();
#pragma unroll 16
        for (int k = 0; k < 64; k++) {
            float a0 = xs[2 * rp][k], a1 = xs[2 * rp + 1][k];
#pragma unroll
            for (int j = 0; j < 4; j++) {
                float wv = ws[k][oq + 16 * j];
                acc[0][j] = fmaf(a0, wv, acc[0][j]);
                acc[1][j] = fmaf(a1, wv, acc[1][j]);
            }
        }
    }
#pragma unroll
    for (int r = 0; r < 2; r++) {
        int bt = bt0 + 2 * rp + r;
        if (bt < 1000) {
#pragma unroll
            for (int j = 0; j < 4; j++)
                g_zpart[((size_t)ks * 1000 + bt) * 64 + oq + 16 * j] = acc[r][j];
        }
    }
}

// ---------------------------------------------------------------------------
// Stage C2: barrier-free scans. Phase 1: 64 lanes each run their own cell's
// 40-step IAF (independent!). Phase 2: parallel 40x64 @ 64x11 mini-GEMM.
// Phase 3: 11 lanes each run their own output neuron's 40-step IAF.
// grid = 25 (b), block = 128. Only 3 barriers total.
// ---------------------------------------------------------------------------
__global__ __launch_bounds__(128) void kC2(const float* __restrict__ w4,
                                           float* __restrict__ out) {
    const int b = blockIdx.x;
    const int tid = threadIdx.x;
    __shared__ float zs[NT * 64];    // z1[t][cell]
    __shared__ float ss[NT * 64];    // spikes1[t][cell]
    __shared__ float z2[NT * 11];    // fc2 pre-activations
    __shared__ float w4s[11 * 65];   // padded to kill bank conflicts

    // parallel load + k-split reduce: 2560 floats = 640 float4
    const float* p0 = g_zpart + (size_t)b * 2560;
    for (int i = tid; i < 640; i += 128) {
        float4 a = *(const float4*)(p0 + 0 * 64000 + i * 4);
        float4 c = *(const float4*)(p0 + 1 * 64000 + i * 4);
        float4 d = *(const float4*)(p0 + 2 * 64000 + i * 4);
        float4 e = *(const float4*)(p0 + 3 * 64000 + i * 4);
        *(float4*)&zs[i * 4] = make_float4(a.x + c.x + d.x + e.x, a.y + c.y + d.y + e.y,
                                           a.z + c.z + d.z + e.z, a.w + c.w + d.w + e.w);
    }
    for (int i = tid; i < 704; i += 128) {
        int o = i >> 6, j = i & 63;
        w4s[o * 65 + j] = w4[i];
    }
    __syncthreads();

    // Phase 1: per-cell IAF scan, barrier-free (cells independent across t)
    if (tid < 64) {
        float v1 = 0.f;
#pragma unroll 8
        for (int t = 0; t < NT; t++) {
            float vv = v1 + zs[t * 64 + tid];
            float s  = (vv >= 1.0f) ? 1.0f : 0.0f;
            vv = (s != 0.f) ? 0.f : vv;
            v1 = fmaxf(vv, -1.0f);
            ss[t * 64 + tid] = s;
        }
    }
    __syncthreads();

    // Phase 2: z2[t][o] = ss[t][:] . w4[o][:]  (440 independent dots)
    for (int i = tid; i < NT * 11; i += 128) {
        int t = i / 11, o = i - 11 * t;
        const float* sp = &ss[t * 64];
        const float* wp = &w4s[o * 65];
        float za = 0.f, zb = 0.f, zc = 0.f, zd = 0.f;
#pragma unroll
        for (int j = 0; j < 64; j += 4) {
            za = fmaf(sp[j],     wp[j],     za);
            zb = fmaf(sp[j + 1], wp[j + 1], zb);
            zc = fmaf(sp[j + 2], wp[j + 2], zc);
            zd = fmaf(sp[j + 3], wp[j + 3], zd);
        }
        z2[i] = (za + zb) + (zc + zd);
    }
    __syncthreads();

    // Phase 3: per-output IAF scan, barrier-free
    if (tid < 11) {
        float v2 = 0.f;
#pragma unroll 8
        for (int t = 0; t < NT; t++) {
            float vv2 = v2 + z2[t * 11 + tid];
            float s2  = (vv2 >= 1.0f) ? 1.0f : 0.0f;
            vv2 = (s2 != 0.f) ? 0.f : vv2;
            v2 = fmaxf(vv2, -1.0f);
            out[(b * NT + t) * 11 + tid] = s2;
        }
    }
}

// ---------------------------------------------------------------------------
extern "C" void kernel_launch(void* const* d_in, const int* in_sizes, int n_in,
                              void* d_out, int out_size) {
    (void)in_sizes; (void)n_in; (void)out_size;
    const float* x  = (const float*)d_in[0];
    const float* w1 = (const float*)d_in[1];
    const float* w2 = (const float*)d_in[2];
    const float* w3 = (const float*)d_in[3];
    const float* w4 = (const float*)d_in[4];
    float* out = (float*)d_out;

    kA<<<dim3(16, 25), 512>>>(x, w1);
    kB<<<dim3(4, 4, 25), 128>>>(w2);
    kC1<<<dim3(32, 4), 256>>>(w3);
    kC2<<<25, 128>>>(w4, out);
}

// round 5
// speedup vs baseline: 3.1189x; 1.3266x over previous
#include <cuda_runtime.h>
#include <cstdint>

#define NB 25
#define NT 40

// Scratch (static device arrays — allocation-free per harness rules)
__device__ float g_buf1[1000 * 8 * 32 * 32];   // stage A pooled spikes [bt][8][32][32]
__device__ float g_buf2[1000 * 16 * 8 * 8];    // stage B pooled spikes [bt][1024]
__device__ float g_zpart[1000 * 4 * 64];       // fc1 partials [bt][ks][64]

__device__ __forceinline__ void cp16(uint32_t dst, const void* src, int bytes) {
    asm volatile("cp.async.cg.shared.global [%0], [%1], 16, %2;\n"
                 :: "r"(dst), "l"(src), "r"(bytes));
}
__device__ __forceinline__ void cp_commit() { asm volatile("cp.async.commit_group;\n" ::); }
__device__ __forceinline__ void cp_wait2()  { asm volatile("cp.async.wait_group 2;\n" ::); }
__device__ __forceinline__ uint32_t saddr(const void* p) {
    return (uint32_t)__cvta_generic_to_shared(p);
}

// ---------------------------------------------------------------------------
// Stage A: conv1 (2->8, 3x3, s2, p1) + IAF over T + 2x2 avgpool, fused.
// grid = (16 row-tiles, 25 b), block = 256, 2 CTAs/SM.
// Thread = (pool-pair of 2 horizontal px) x 4 oc. 4-buffer cp.async ring,
// 2 t-steps per barrier pair. smem row: pad at [3], data at [4+iw].
// ---------------------------------------------------------------------------
__global__ __launch_bounds__(256, 2) void kA(const float* __restrict__ x,
                                             const float* __restrict__ w1) {
    const int tr = blockIdx.x;   // output rows [4*tr, 4*tr+4)
    const int b  = blockIdx.y;
    const int tid = threadIdx.x;

    __shared__ float sw[144];
    __shared__ __align__(16) float sx[4][2][9][132]; // [buf][ic][r][4+iw]; [3]=pad
    __shared__ float spool[2][8][2][32];             // [step][oc][prow][pc]

    if (tid < 144) sw[tid] = w1[tid];
    if (tid < 72) { int bu = tid / 18, r = tid % 18; sx[bu][r / 9][r % 9][3] = 0.f; }

    // tid bits: [0:3]=pcl, [4]=rowlsb, [5]=pch, [6]=rowhi, [7]=og
    const int pcl    = tid & 15;
    const int rowlsb = (tid >> 4) & 1;
    const int pch    = (tid >> 5) & 1;
    const int rowhi  = (tid >> 6) & 1;
    const int og     = (tid >> 7) & 1;
    const int pc  = pcl + 16 * pch;      // pool col 0..31 (= pair ow 2pc,2pc+1)
    const int row = rowlsb + 2 * rowhi;  // local output row 0..3
    const int ihb = 8 * tr - 1;

    // load slots: 2ch x 9row x 32 float4 = 576 over 256 threads
    int sch[3], sr[3], sc[3], sih[3]; bool sact[3];
#pragma unroll
    for (int k = 0; k < 3; k++) {
        int i = tid + k * 256;
        sact[k] = (i < 576);
        int ii = sact[k] ? i : 0;
        sch[k] = (ii >= 288) ? 1 : 0;
        int rem = ii - sch[k] * 288;
        sr[k] = rem >> 5; sc[k] = rem & 31; sih[k] = ihb + sr[k];
    }

    auto issue = [&](int t, int bu) {
        const float* xp = x + (size_t)(b * NT + t) * 32768;
#pragma unroll
        for (int k = 0; k < 3; k++) {
            if (!sact[k]) continue;
            int ih = (sih[k] < 0) ? 0 : sih[k];
            int by = ((unsigned)sih[k] < 128u) ? 16 : 0;
            cp16(saddr(&sx[bu][sch[k]][sr[k]][4 + sc[k] * 4]),
                 xp + (sch[k] * 128 + ih) * 128 + sc[k] * 4, by);
        }
    };

    issue(0, 0); cp_commit();
    issue(1, 1); cp_commit();
    __syncthreads();   // sw + pads visible

    // weights: wr[ic][kh][kw][i], oc = og*4+i ; w1 layout [oc][ic][3][3]
    float wr[2][3][3][4];
#pragma unroll
    for (int ic = 0; ic < 2; ic++)
#pragma unroll
      for (int kh = 0; kh < 3; kh++)
#pragma unroll
        for (int kw = 0; kw < 3; kw++)
#pragma unroll
          for (int i = 0; i < 4; i++)
            wr[ic][kh][kw][i] = sw[(((og * 4 + i) * 2 + ic) * 3 + kh) * 3 + kw];

    float v[2][4];
#pragma unroll
    for (int px = 0; px < 2; px++)
#pragma unroll
      for (int i = 0; i < 4; i++) v[px][i] = 0.f;

    auto compute = [&](int bu, int sb) {
        float acc[2][4];
#pragma unroll
        for (int px = 0; px < 2; px++)
#pragma unroll
          for (int i = 0; i < 4; i++) acc[px][i] = 0.f;
#pragma unroll
        for (int ic = 0; ic < 2; ic++)
#pragma unroll
          for (int kh = 0; kh < 3; kh++) {
            const float* rp = &sx[bu][ic][2 * row + kh][0];
            float  xm = rp[3 + 4 * pc];
            float4 r4 = *(const float4*)&rp[4 + 4 * pc];
#pragma unroll
            for (int i = 0; i < 4; i++) {
                float w0 = wr[ic][kh][0][i], w1r = wr[ic][kh][1][i], w2r = wr[ic][kh][2][i];
                acc[0][i] = fmaf(xm,   w0,  acc[0][i]);
                acc[0][i] = fmaf(r4.x, w1r, acc[0][i]);
                acc[0][i] = fmaf(r4.y, w2r, acc[0][i]);
                acc[1][i] = fmaf(r4.y, w0,  acc[1][i]);
                acc[1][i] = fmaf(r4.z, w1r, acc[1][i]);
                acc[1][i] = fmaf(r4.w, w2r, acc[1][i]);
            }
          }
        // IAF + pool: horizontal pair in-thread, vertical pair via shfl_xor(16)
#pragma unroll
        for (int i = 0; i < 4; i++) {
            float h = 0.f;
#pragma unroll
            for (int px = 0; px < 2; px++) {
                float vv = v[px][i] + acc[px][i];
                float s  = (vv >= 1.0f) ? 1.0f : 0.0f;
                vv = (s != 0.f) ? 0.f : vv;
                v[px][i] = fmaxf(vv, -1.0f);
                h += s;
            }
            h += __shfl_xor_sync(0xffffffffu, h, 16);
            if (rowlsb == 0) spool[sb][og * 4 + i][rowhi][pc] = h * 0.25f;
        }
    };

    for (int t = 0; t < NT; t += 2) {
        if (t + 2 < NT) issue(t + 2, (t + 2) & 3);
        cp_commit();
        if (t + 3 < NT) issue(t + 3, (t + 3) & 3);
        cp_commit();
        cp_wait2();          // tiles t, t+1 complete (this thread)
        __syncthreads();     // visible to all; spool reusable

        compute(t & 3, 0);
        compute((t + 1) & 3, 1);
        __syncthreads();

        // pooled stores: 2 steps x 512 values, coalesced
#pragma unroll
        for (int sb = 0; sb < 2; sb++) {
            float* outp = g_buf1 + (size_t)(b * NT + t + sb) * 8192;
#pragma unroll
            for (int k = 0; k < 2; k++) {
                int i = tid + k * 256;
                int oc = i >> 6, prow = (i >> 5) & 1, pcc = i & 31;
                outp[oc * 1024 + (2 * tr + prow) * 32 + pcc] = spool[sb][oc][prow][pcc];
            }
        }
    }
}

// ---------------------------------------------------------------------------
// Stage B: conv2 (8->16, 3x3, s2, p1) + IAF + 2x2 avgpool, fused.
// grid = (4 row-tiles, 2 oc-splits, 25 b), block = 128, 2 CTAs/SM.
// Thread = 2 horizontal px x 2 oc; 8 oc per CTA. 4-buffer ring, 2-step loop.
// ---------------------------------------------------------------------------
__global__ __launch_bounds__(128, 2) void kB(const float* __restrict__ w2) {
    const int tr = blockIdx.x;   // out rows [4*tr, 4*tr+4)
    const int os = blockIdx.y;   // oc base = 8*os
    const int b  = blockIdx.z;
    const int tid = threadIdx.x;

    __shared__ float sw[576];
    __shared__ __align__(16) float sx[4][8][9][36]; // [buf][ic][r][4+iw]; [3]=pad
    __shared__ float spool[2][8][2][8];             // [step][oc][prow][pc]

    for (int i = tid; i < 576; i += 128) sw[i] = w2[os * 576 + i];
    for (int i = tid; i < 288; i += 128) {
        int bu = i / 72, r = i % 72;
        sx[bu][r / 9][r % 9][3] = 0.f;
    }

    // tid bits: [0:2]=pc, [3]=rowlsb, [4:5]=ocp, [6]=rowhi
    const int pc     = tid & 7;
    const int rowlsb = (tid >> 3) & 1;
    const int ocp    = (tid >> 4) & 3;
    const int rowhi  = (tid >> 6) & 1;
    const int row    = rowlsb + 2 * rowhi;
    const int ihb = 8 * tr - 1;

    // load slots: 8ch x 9row x 8 float4 = 576 over 128 thr -> 4 full + 1 partial
    int lch[5], lr[5], lc[5], lih[5]; bool lact[5];
#pragma unroll
    for (int k = 0; k < 5; k++) {
        int i = tid + k * 128;
        lact[k] = (i < 576);
        int ii = lact[k] ? i : 0;
        lch[k] = ii / 72; int rem = ii - lch[k] * 72;
        lr[k] = rem >> 3; lc[k] = rem & 7; lih[k] = ihb + lr[k];
    }

    auto issue = [&](int t, int bu) {
        const float* inp = g_buf1 + (size_t)(b * NT + t) * 8192;
#pragma unroll
        for (int k = 0; k < 5; k++) {
            if (!lact[k]) continue;
            int ih = (lih[k] < 0) ? 0 : lih[k];
            int by = ((unsigned)lih[k] < 32u) ? 16 : 0;
            cp16(saddr(&sx[bu][lch[k]][lr[k]][4 + lc[k] * 4]),
                 inp + (lch[k] * 32 + ih) * 32 + lc[k] * 4, by);
        }
    };

    issue(0, 0); cp_commit();
    issue(1, 1); cp_commit();
    __syncthreads();

    // weights: 2 ocs per thread (oc = os*8 + ocp*2 + j); w2 row = 72 floats
    float wrg[8][3][3][2];
#pragma unroll
    for (int ic = 0; ic < 8; ic++)
#pragma unroll
      for (int kh = 0; kh < 3; kh++)
#pragma unroll
        for (int kw = 0; kw < 3; kw++)
#pragma unroll
          for (int j = 0; j < 2; j++)
            wrg[ic][kh][kw][j] = sw[(ocp * 2 + j) * 72 + ic * 9 + kh * 3 + kw];

    float v[2][2];
    v[0][0] = v[0][1] = v[1][0] = v[1][1] = 0.f;

    auto compute = [&](int bu, int sb) {
        float acc[2][2];
        acc[0][0] = acc[0][1] = acc[1][0] = acc[1][1] = 0.f;
#pragma unroll
        for (int ic = 0; ic < 8; ic++)
#pragma unroll
          for (int kh = 0; kh < 3; kh++) {
            const float* rp = &sx[bu][ic][2 * row + kh][0];
            float  xm = rp[3 + 4 * pc];
            float4 r4 = *(const float4*)&rp[4 + 4 * pc];
#pragma unroll
            for (int j = 0; j < 2; j++) {
                float w0 = wrg[ic][kh][0][j], w1r = wrg[ic][kh][1][j], w2r = wrg[ic][kh][2][j];
                acc[0][j] = fmaf(xm,   w0,  acc[0][j]);
                acc[0][j] = fmaf(r4.x, w1r, acc[0][j]);
                acc[0][j] = fmaf(r4.y, w2r, acc[0][j]);
                acc[1][j] = fmaf(r4.y, w0,  acc[1][j]);
                acc[1][j] = fmaf(r4.z, w1r, acc[1][j]);
                acc[1][j] = fmaf(r4.w, w2r, acc[1][j]);
            }
          }
#pragma unroll
        for (int j = 0; j < 2; j++) {
            float h = 0.f;
#pragma unroll
            for (int px = 0; px < 2; px++) {
                float vv = v[px][j] + acc[px][j];
                float s  = (vv >= 1.0f) ? 1.0f : 0.0f;
                vv = (s != 0.f) ? 0.f : vv;
                v[px][j] = fmaxf(vv, -1.0f);
                h += s;
            }
            h += __shfl_xor_sync(0xffffffffu, h, 8);   // vertical pair (rowlsb)
            if (rowlsb == 0) spool[sb][ocp * 2 + j][rowhi][pc] = h * 0.25f;
        }
    };

    for (int t = 0; t < NT; t += 2) {
        if (t + 2 < NT) issue(t + 2, (t + 2) & 3);
        cp_commit();
        if (t + 3 < NT) issue(t + 3, (t + 3) & 3);
        cp_commit();
        cp_wait2();
        __syncthreads();

        compute(t & 3, 0);
        compute((t + 1) & 3, 1);
        __syncthreads();

#pragma unroll
        for (int sb = 0; sb < 2; sb++) {
            int oc = tid >> 4, prow = (tid >> 3) & 1, pcc = tid & 7;
            g_buf2[(size_t)(b * NT + t + sb) * 1024 + (os * 8 + oc) * 64 +
                   (2 * tr + prow) * 8 + pcc] = spool[sb][oc][prow][pcc];
        }
    }
}

// ---------------------------------------------------------------------------
// Stage C1: fc1 partial GEMM  z[bt,64] = buf2[bt,1024] @ w3^T, k-split x4.
// grid = (32 bt-tiles of 32 rows, 4 k-splits), block 256, thread tile 2x4.
// zpart layout: [bt][ks][64] (contiguous per bt for kC2).
// ---------------------------------------------------------------------------
__global__ __launch_bounds__(256) void kC1(const float* __restrict__ w3) {
    const int bt0 = blockIdx.x * 32;
    const int ks  = blockIdx.y;
    const int tid = threadIdx.x;
    __shared__ float xs[32][64];
    __shared__ float ws[64][65];
    const int rp = tid >> 4, oq = tid & 15;

    float acc[2][4];
#pragma unroll
    for (int r = 0; r < 2; r++)
#pragma unroll
      for (int j = 0; j < 4; j++) acc[r][j] = 0.f;

    for (int kc = 0; kc < 4; kc++) {
        int koff = ks * 256 + kc * 64;
        __syncthreads();
        for (int i = tid; i < 512; i += 256) {
            int r = i >> 4, c4 = i & 15;
            int bt = bt0 + r;
            float4 vv = make_float4(0.f, 0.f, 0.f, 0.f);
            if (bt < 1000) vv = *(const float4*)(g_buf2 + (size_t)bt * 1024 + koff + c4 * 4);
            *(float4*)&xs[r][c4 * 4] = vv;
        }
        for (int i = tid; i < 4096; i += 256) {   // transpose w3 chunk into smem
            int o = i >> 6, k = i & 63;
            ws[k][o] = w3[o * 1024 + koff + k];
        }
        __syncthreads();
#pragma unroll 16
        for (int k = 0; k < 64; k++) {
            float a0 = xs[2 * rp][k], a1 = xs[2 * rp + 1][k];
#pragma unroll
            for (int j = 0; j < 4; j++) {
                float wv = ws[k][oq + 16 * j];
                acc[0][j] = fmaf(a0, wv, acc[0][j]);
                acc[1][j] = fmaf(a1, wv, acc[1][j]);
            }
        }
    }
#pragma unroll
    for (int r = 0; r < 2; r++) {
        int bt = bt0 + 2 * rp + r;
        if (bt < 1000) {
#pragma unroll
            for (int j = 0; j < 4; j++)
                g_zpart[((size_t)bt * 4 + ks) * 64 + oq + 16 * j] = acc[r][j];
        }
    }
}

// ---------------------------------------------------------------------------
// Stage C2: contiguous gather + barrier-free scans (per-cell IAF is
// independent across t). grid = 25 (b), block = 128. 3 barriers total.
// ---------------------------------------------------------------------------
__global__ __launch_bounds__(128) void kC2(const float* __restrict__ w4,
                                           float* __restrict__ out) {
    const int b = blockIdx.x;
    const int tid = threadIdx.x;
    __shared__ float zs[NT * 64];    // z1[t][cell]
    __shared__ float ss[NT * 64];    // spikes1[t][cell]
    __shared__ float z2[NT * 11];    // fc2 pre-activations
    __shared__ float w4s[11 * 65];   // padded

    // contiguous load + k-split reduce: [40][4][64] -> [40][64]
    const float* p0 = g_zpart + (size_t)b * NT * 256;
    for (int i = tid; i < 640; i += 128) {
        int t = i >> 4, c4 = i & 15;
        const float* q = p0 + t * 256 + c4 * 4;
        float4 a = *(const float4*)(q);
        float4 c = *(const float4*)(q + 64);
        float4 d = *(const float4*)(q + 128);
        float4 e = *(const float4*)(q + 192);
        *(float4*)&zs[t * 64 + c4 * 4] =
            make_float4(a.x + c.x + d.x + e.x, a.y + c.y + d.y + e.y,
                        a.z + c.z + d.z + e.z, a.w + c.w + d.w + e.w);
    }
    for (int i = tid; i < 704; i += 128) {
        int o = i >> 6, j = i & 63;
        w4s[o * 65 + j] = w4[i];
    }
    __syncthreads();

    // Phase 1: per-cell IAF scan, barrier-free
    if (tid < 64) {
        float v1 = 0.f;
#pragma unroll 8
        for (int t = 0; t < NT; t++) {
            float vv = v1 + zs[t * 64 + tid];
            float s  = (vv >= 1.0f) ? 1.0f : 0.0f;
            vv = (s != 0.f) ? 0.f : vv;
            v1 = fmaxf(vv, -1.0f);
            ss[t * 64 + tid] = s;
        }
    }
    __syncthreads();

    // Phase 2: z2[t][o] = ss[t][:] . w4[o][:]
    for (int i = tid; i < NT * 11; i += 128) {
        int t = i / 11, o = i - 11 * t;
        const float* sp = &ss[t * 64];
        const float* wp = &w4s[o * 65];
        float za = 0.f, zb = 0.f, zc = 0.f, zd = 0.f;
#pragma unroll
        for (int j = 0; j < 64; j += 4) {
            za = fmaf(sp[j],     wp[j],     za);
            zb = fmaf(sp[j + 1], wp[j + 1], zb);
            zc = fmaf(sp[j + 2], wp[j + 2], zc);
            zd = fmaf(sp[j + 3], wp[j + 3], zd);
        }
        z2[i] = (za + zb) + (zc + zd);
    }
    __syncthreads();

    // Phase 3: per-output IAF scan, barrier-free
    if (tid < 11) {
        float v2 = 0.f;
#pragma unroll 8
        for (int t = 0; t < NT; t++) {
            float vv2 = v2 + z2[t * 11 + tid];
            float s2  = (vv2 >= 1.0f) ? 1.0f : 0.0f;
            vv2 = (s2 != 0.f) ? 0.f : vv2;
            v2 = fmaxf(vv2, -1.0f);
            out[(b * NT + t) * 11 + tid] = s2;
        }
    }
}

// ---------------------------------------------------------------------------
extern "C" void kernel_launch(void* const* d_in, const int* in_sizes, int n_in,
                              void* d_out, int out_size) {
    (void)in_sizes; (void)n_in; (void)out_size;
    const float* x  = (const float*)d_in[0];
    const float* w1 = (const float*)d_in[1];
    const float* w2 = (const float*)d_in[2];
    const float* w3 = (const float*)d_in[3];
    const float* w4 = (const float*)d_in[4];
    float* out = (float*)d_out;

    kA<<<dim3(16, 25), 256>>>(x, w1);
    kB<<<dim3(4, 2, 25), 128>>>(w2);
    kC1<<<dim3(32, 4), 256>>>(w3);
    kC2<<<25, 128>>>(w4, out);
}

// round 6
// speedup vs baseline: 3.2174x; 1.0316x over previous
#include <cuda_runtime.h>
#include <cstdint>

#define NB 25
#define NT 40

// Scratch (static device arrays — allocation-free per harness rules)
__device__ float g_buf1[1000 * 8 * 32 * 32];   // stage A pooled spikes [bt][8][32][32]
__device__ float g_buf2[1000 * 16 * 8 * 8];    // stage B pooled spikes [bt][1024]
__device__ float g_zpart[1000 * 4 * 64];       // fc1 partials [bt][ks][64]

__device__ __forceinline__ void cp16(uint32_t dst, const void* src, int bytes) {
    asm volatile("cp.async.cg.shared.global [%0], [%1], 16, %2;\n"
                 :: "r"(dst), "l"(src), "r"(bytes));
}
__device__ __forceinline__ void cp_commit() { asm volatile("cp.async.commit_group;\n" ::); }
__device__ __forceinline__ void cp_wait2()  { asm volatile("cp.async.wait_group 2;\n" ::); }
__device__ __forceinline__ uint32_t saddr(const void* p) {
    return (uint32_t)__cvta_generic_to_shared(p);
}

// ---- packed f32x2 helpers (sm_103a) ---------------------------------------
__device__ __forceinline__ unsigned long long pk2(float lo, float hi) {
    unsigned long long r;
    asm("mov.b64 %0, {%1, %2};" : "=l"(r) : "f"(lo), "f"(hi));
    return r;
}
__device__ __forceinline__ unsigned long long bcast2(float x) {
    unsigned long long r;
    asm("mov.b64 %0, {%1, %1};" : "=l"(r) : "f"(x));
    return r;
}
__device__ __forceinline__ void fma2(unsigned long long& d,
                                     unsigned long long a, unsigned long long b) {
    asm("fma.rn.f32x2 %0, %1, %2, %0;" : "+l"(d) : "l"(a), "l"(b));
}
__device__ __forceinline__ void unpk2(unsigned long long v, float& lo, float& hi) {
    asm("mov.b64 {%0, %1}, %2;" : "=f"(lo), "=f"(hi) : "l"(v));
}

// ---------------------------------------------------------------------------
// Stage A: conv1 (2->8, 3x3, s2, p1) + IAF over T + 2x2 avgpool, fused.
// grid = (16 row-tiles, 25 b), block = 256, 2 CTAs/SM.
// Thread = 2 horizontal px x 4 oc (as 2 f32x2 oc-pairs). 4-buffer cp.async
// ring, 2 t-steps per barrier pair. smem row: pad at [3], data at [4+iw].
// ---------------------------------------------------------------------------
__global__ __launch_bounds__(256, 2) void kA(const float* __restrict__ x,
                                             const float* __restrict__ w1) {
    const int tr = blockIdx.x;   // output rows [4*tr, 4*tr+4)
    const int b  = blockIdx.y;
    const int tid = threadIdx.x;

    __shared__ float sw[144];
    __shared__ __align__(16) float sx[4][2][9][132]; // [buf][ic][r][4+iw]; [3]=pad
    __shared__ float spool[2][8][2][32];             // [step][oc][prow][pc]

    if (tid < 144) sw[tid] = w1[tid];
    if (tid < 72) { int bu = tid / 18, r = tid % 18; sx[bu][r / 9][r % 9][3] = 0.f; }

    // tid bits: [0:3]=pcl, [4]=rowlsb, [5]=pch, [6]=rowhi, [7]=og
    const int pcl    = tid & 15;
    const int rowlsb = (tid >> 4) & 1;
    const int pch    = (tid >> 5) & 1;
    const int rowhi  = (tid >> 6) & 1;
    const int og     = (tid >> 7) & 1;
    const int pc  = pcl + 16 * pch;      // pool col 0..31 (= pair ow 2pc,2pc+1)
    const int row = rowlsb + 2 * rowhi;  // local output row 0..3
    const int ihb = 8 * tr - 1;

    // load slots: 2ch x 9row x 32 float4 = 576 over 256 threads
    int sch[3], sr[3], sc[3], sih[3]; bool sact[3];
#pragma unroll
    for (int k = 0; k < 3; k++) {
        int i = tid + k * 256;
        sact[k] = (i < 576);
        int ii = sact[k] ? i : 0;
        sch[k] = (ii >= 288) ? 1 : 0;
        int rem = ii - sch[k] * 288;
        sr[k] = rem >> 5; sc[k] = rem & 31; sih[k] = ihb + sr[k];
    }

    auto issue = [&](int t, int bu) {
        const float* xp = x + (size_t)(b * NT + t) * 32768;
#pragma unroll
        for (int k = 0; k < 3; k++) {
            if (!sact[k]) continue;
            int ih = (sih[k] < 0) ? 0 : sih[k];
            int by = ((unsigned)sih[k] < 128u) ? 16 : 0;
            cp16(saddr(&sx[bu][sch[k]][sr[k]][4 + sc[k] * 4]),
                 xp + (sch[k] * 128 + ih) * 128 + sc[k] * 4, by);
        }
    };

    issue(0, 0); cp_commit();
    issue(1, 1); cp_commit();
    __syncthreads();   // sw + pads visible

    // packed weights: wq[ic][kh][kw][p] = {w(oc=og*4+2p), w(oc=og*4+2p+1)}
    unsigned long long wq[2][3][3][2];
#pragma unroll
    for (int ic = 0; ic < 2; ic++)
#pragma unroll
      for (int kh = 0; kh < 3; kh++)
#pragma unroll
        for (int kw = 0; kw < 3; kw++)
#pragma unroll
          for (int p = 0; p < 2; p++) {
            float wlo = sw[(((og * 4 + 2 * p)     * 2 + ic) * 3 + kh) * 3 + kw];
            float whi = sw[(((og * 4 + 2 * p + 1) * 2 + ic) * 3 + kh) * 3 + kw];
            wq[ic][kh][kw][p] = pk2(wlo, whi);
          }

    float v[2][4];
#pragma unroll
    for (int px = 0; px < 2; px++)
#pragma unroll
      for (int i = 0; i < 4; i++) v[px][i] = 0.f;

    auto compute = [&](int bu, int sb) {
        unsigned long long a2[2][2];      // [px][pair]
        a2[0][0] = a2[0][1] = a2[1][0] = a2[1][1] = 0ull;
#pragma unroll
        for (int ic = 0; ic < 2; ic++)
#pragma unroll
          for (int kh = 0; kh < 3; kh++) {
            const float* rp = &sx[bu][ic][2 * row + kh][0];
            float  xm = rp[3 + 4 * pc];
            float4 r4 = *(const float4*)&rp[4 + 4 * pc];
            unsigned long long X;
            X = bcast2(xm);                       // px0 kw0
            fma2(a2[0][0], X, wq[ic][kh][0][0]);
            fma2(a2[0][1], X, wq[ic][kh][0][1]);
            X = bcast2(r4.x);                     // px0 kw1
            fma2(a2[0][0], X, wq[ic][kh][1][0]);
            fma2(a2[0][1], X, wq[ic][kh][1][1]);
            X = bcast2(r4.y);                     // px0 kw2 + px1 kw0 (shared)
            fma2(a2[0][0], X, wq[ic][kh][2][0]);
            fma2(a2[0][1], X, wq[ic][kh][2][1]);
            fma2(a2[1][0], X, wq[ic][kh][0][0]);
            fma2(a2[1][1], X, wq[ic][kh][0][1]);
            X = bcast2(r4.z);                     // px1 kw1
            fma2(a2[1][0], X, wq[ic][kh][1][0]);
            fma2(a2[1][1], X, wq[ic][kh][1][1]);
            X = bcast2(r4.w);                     // px1 kw2
            fma2(a2[1][0], X, wq[ic][kh][2][0]);
            fma2(a2[1][1], X, wq[ic][kh][2][1]);
          }
        // unpack -> IAF + pool (horizontal pair in-thread, vertical via shfl)
        float acc[2][4];
#pragma unroll
        for (int px = 0; px < 2; px++) {
            unpk2(a2[px][0], acc[px][0], acc[px][1]);
            unpk2(a2[px][1], acc[px][2], acc[px][3]);
        }
#pragma unroll
        for (int i = 0; i < 4; i++) {
            float h = 0.f;
#pragma unroll
            for (int px = 0; px < 2; px++) {
                float vv = v[px][i] + acc[px][i];
                float s  = (vv >= 1.0f) ? 1.0f : 0.0f;
                vv = (s != 0.f) ? 0.f : vv;
                v[px][i] = fmaxf(vv, -1.0f);
                h += s;
            }
            h += __shfl_xor_sync(0xffffffffu, h, 16);
            if (rowlsb == 0) spool[sb][og * 4 + i][rowhi][pc] = h * 0.25f;
        }
    };

    for (int t = 0; t < NT; t += 2) {
        if (t + 2 < NT) issue(t + 2, (t + 2) & 3);
        cp_commit();
        if (t + 3 < NT) issue(t + 3, (t + 3) & 3);
        cp_commit();
        cp_wait2();          // tiles t, t+1 complete (this thread)
        __syncthreads();     // visible to all; spool reusable

        compute(t & 3, 0);
        compute((t + 1) & 3, 1);
        __syncthreads();

        // pooled stores: 2 steps x 512 values, coalesced
#pragma unroll
        for (int sb = 0; sb < 2; sb++) {
            float* outp = g_buf1 + (size_t)(b * NT + t + sb) * 8192;
#pragma unroll
            for (int k = 0; k < 2; k++) {
                int i = tid + k * 256;
                int oc = i >> 6, prow = (i >> 5) & 1, pcc = i & 31;
                outp[oc * 1024 + (2 * tr + prow) * 32 + pcc] = spool[sb][oc][prow][pcc];
            }
        }
    }
}

// ---------------------------------------------------------------------------
// Stage B: conv2 (8->16, 3x3, s2, p1) + IAF + 2x2 avgpool, fused.
// grid = (4 row-tiles, 2 oc-splits, 25 b), block = 128, 2 CTAs/SM.
// Thread = 2 horizontal px x 2 oc; 8 oc per CTA. 4-buffer ring, 2-step loop.
// ---------------------------------------------------------------------------
__global__ __launch_bounds__(128, 2) void kB(const float* __restrict__ w2) {
    const int tr = blockIdx.x;   // out rows [4*tr, 4*tr+4)
    const int os = blockIdx.y;   // oc base = 8*os
    const int b  = blockIdx.z;
    const int tid = threadIdx.x;

    __shared__ float sw[576];
    __shared__ __align__(16) float sx[4][8][9][36]; // [buf][ic][r][4+iw]; [3]=pad
    __shared__ float spool[2][8][2][8];             // [step][oc][prow][pc]

    for (int i = tid; i < 576; i += 128) sw[i] = w2[os * 576 + i];
    for (int i = tid; i < 288; i += 128) {
        int bu = i / 72, r = i % 72;
        sx[bu][r / 9][r % 9][3] = 0.f;
    }

    // tid bits: [0:2]=pc, [3]=rowlsb, [4:5]=ocp, [6]=rowhi
    const int pc     = tid & 7;
    const int rowlsb = (tid >> 3) & 1;
    const int ocp    = (tid >> 4) & 3;
    const int rowhi  = (tid >> 6) & 1;
    const int row    = rowlsb + 2 * rowhi;
    const int ihb = 8 * tr - 1;

    // load slots: 8ch x 9row x 8 float4 = 576 over 128 thr -> 4 full + 1 partial
    int lch[5], lr[5], lc[5], lih[5]; bool lact[5];
#pragma unroll
    for (int k = 0; k < 5; k++) {
        int i = tid + k * 128;
        lact[k] = (i < 576);
        int ii = lact[k] ? i : 0;
        lch[k] = ii / 72; int rem = ii - lch[k] * 72;
        lr[k] = rem >> 3; lc[k] = rem & 7; lih[k] = ihb + lr[k];
    }

    auto issue = [&](int t, int bu) {
        const float* inp = g_buf1 + (size_t)(b * NT + t) * 8192;
#pragma unroll
        for (int k = 0; k < 5; k++) {
            if (!lact[k]) continue;
            int ih = (lih[k] < 0) ? 0 : lih[k];
            int by = ((unsigned)lih[k] < 32u) ? 16 : 0;
            cp16(saddr(&sx[bu][lch[k]][lr[k]][4 + lc[k] * 4]),
                 inp + (lch[k] * 32 + ih) * 32 + lc[k] * 4, by);
        }
    };

    issue(0, 0); cp_commit();
    issue(1, 1); cp_commit();
    __syncthreads();

    // weights: 2 ocs per thread (oc = os*8 + ocp*2 + j); w2 row = 72 floats
    float wrg[8][3][3][2];
#pragma unroll
    for (int ic = 0; ic < 8; ic++)
#pragma unroll
      for (int kh = 0; kh < 3; kh++)
#pragma unroll
        for (int kw = 0; kw < 3; kw++)
#pragma unroll
          for (int j = 0; j < 2; j++)
            wrg[ic][kh][kw][j] = sw[(ocp * 2 + j) * 72 + ic * 9 + kh * 3 + kw];

    float v[2][2];
    v[0][0] = v[0][1] = v[1][0] = v[1][1] = 0.f;

    auto compute = [&](int bu, int sb) {
        float acc[2][2];
        acc[0][0] = acc[0][1] = acc[1][0] = acc[1][1] = 0.f;
#pragma unroll
        for (int ic = 0; ic < 8; ic++)
#pragma unroll
          for (int kh = 0; kh < 3; kh++) {
            const float* rp = &sx[bu][ic][2 * row + kh][0];
            float  xm = rp[3 + 4 * pc];
            float4 r4 = *(const float4*)&rp[4 + 4 * pc];
#pragma unroll
            for (int j = 0; j < 2; j++) {
                float w0 = wrg[ic][kh][0][j], w1r = wrg[ic][kh][1][j], w2r = wrg[ic][kh][2][j];
                acc[0][j] = fmaf(xm,   w0,  acc[0][j]);
                acc[0][j] = fmaf(r4.x, w1r, acc[0][j]);
                acc[0][j] = fmaf(r4.y, w2r, acc[0][j]);
                acc[1][j] = fmaf(r4.y, w0,  acc[1][j]);
                acc[1][j] = fmaf(r4.z, w1r, acc[1][j]);
                acc[1][j] = fmaf(r4.w, w2r, acc[1][j]);
            }
          }
#pragma unroll
        for (int j = 0; j < 2; j++) {
            float h = 0.f;
#pragma unroll
            for (int px = 0; px < 2; px++) {
                float vv = v[px][j] + acc[px][j];
                float s  = (vv >= 1.0f) ? 1.0f : 0.0f;
                vv = (s != 0.f) ? 0.f : vv;
                v[px][j] = fmaxf(vv, -1.0f);
                h += s;
            }
            h += __shfl_xor_sync(0xffffffffu, h, 8);   // vertical pair (rowlsb)
            if (rowlsb == 0) spool[sb][ocp * 2 + j][rowhi][pc] = h * 0.25f;
        }
    };

    for (int t = 0; t < NT; t += 2) {
        if (t + 2 < NT) issue(t + 2, (t + 2) & 3);
        cp_commit();
        if (t + 3 < NT) issue(t + 3, (t + 3) & 3);
        cp_commit();
        cp_wait2();
        __syncthreads();

        compute(t & 3, 0);
        compute((t + 1) & 3, 1);
        __syncthreads();

#pragma unroll
        for (int sb = 0; sb < 2; sb++) {
            int oc = tid >> 4, prow = (tid >> 3) & 1, pcc = tid & 7;
            g_buf2[(size_t)(b * NT + t + sb) * 1024 + (os * 8 + oc) * 64 +
                   (2 * tr + prow) * 8 + pcc] = spool[sb][oc][prow][pcc];
        }
    }
}

// ---------------------------------------------------------------------------
// Stage C1: fc1 partial GEMM  z[bt,64] = buf2[bt,1024] @ w3^T, k-split x4.
// grid = (32 bt-tiles of 32 rows, 4 k-splits), block 256, thread tile 2x4.
// zpart layout: [bt][ks][64] (contiguous per bt for kC2).
// ---------------------------------------------------------------------------
__global__ __launch_bounds__(256) void kC1(const float* __restrict__ w3) {
    const int bt0 = blockIdx.x * 32;
    const int ks  = blockIdx.y;
    const int tid = threadIdx.x;
    __shared__ float xs[32][64];
    __shared__ float ws[64][65];
    const int rp = tid >> 4, oq = tid & 15;

    float acc[2][4];
#pragma unroll
    for (int r = 0; r < 2; r++)
#pragma unroll
      for (int j = 0; j < 4; j++) acc[r][j] = 0.f;

    for (int kc = 0; kc < 4; kc++) {
        int koff = ks * 256 + kc * 64;
        __syncthreads();
        for (int i = tid; i < 512; i += 256) {
            int r = i >> 4, c4 = i & 15;
            int bt = bt0 + r;
            float4 vv = make_float4(0.f, 0.f, 0.f, 0.f);
            if (bt < 1000) vv = *(const float4*)(g_buf2 + (size_t)bt * 1024 + koff + c4 * 4);
            *(float4*)&xs[r][c4 * 4] = vv;
        }
        for (int i = tid; i < 4096; i += 256) {   // transpose w3 chunk into smem
            int o = i >> 6, k = i & 63;
            ws[k][o] = w3[o * 1024 + koff + k];
        }
        __syncthreads();
#pragma unroll 16
        for (int k = 0; k < 64; k++) {
            float a0 = xs[2 * rp][k], a1 = xs[2 * rp + 1][k];
#pragma unroll
            for (int j = 0; j < 4; j++) {
                float wv = ws[k][oq + 16 * j];
                acc[0][j] = fmaf(a0, wv, acc[0][j]);
                acc[1][j] = fmaf(a1, wv, acc[1][j]);
            }
        }
    }
#pragma unroll
    for (int r = 0; r < 2; r++) {
        int bt = bt0 + 2 * rp + r;
        if (bt < 1000) {
#pragma unroll
            for (int j = 0; j < 4; j++)
                g_zpart[((size_t)bt * 4 + ks) * 64 + oq + 16 * j] = acc[r][j];
        }
    }
}

// ---------------------------------------------------------------------------
// Stage C2: contiguous gather + barrier-free scans (per-cell IAF is
// independent across t). grid = 25 (b), block = 256. 3 barriers total.
// ---------------------------------------------------------------------------
__global__ __launch_bounds__(256) void kC2(const float* __restrict__ w4,
                                           float* __restrict__ out) {
    const int b = blockIdx.x;
    const int tid = threadIdx.x;
    __shared__ float zs[NT * 64];    // z1[t][cell]
    __shared__ float ss[NT * 64];    // spikes1[t][cell]
    __shared__ float z2[NT * 11];    // fc2 pre-activations
    __shared__ float w4s[11 * 65];   // padded

    // contiguous load + k-split reduce: [40][4][64] -> [40][64]
    const float* p0 = g_zpart + (size_t)b * NT * 256;
    for (int i = tid; i < 640; i += 256) {
        int t = i >> 4, c4 = i & 15;
        const float* q = p0 + t * 256 + c4 * 4;
        float4 a = *(const float4*)(q);
        float4 c = *(const float4*)(q + 64);
        float4 d = *(const float4*)(q + 128);
        float4 e = *(const float4*)(q + 192);
        *(float4*)&zs[t * 64 + c4 * 4] =
            make_float4(a.x + c.x + d.x + e.x, a.y + c.y + d.y + e.y,
                        a.z + c.z + d.z + e.z, a.w + c.w + d.w + e.w);
    }
    for (int i = tid; i < 704; i += 256) {
        int o = i >> 6, j = i & 63;
        w4s[o * 65 + j] = w4[i];
    }
    __syncthreads();

    // Phase 1: per-cell IAF scan, barrier-free
    if (tid < 64) {
        float v1 = 0.f;
#pragma unroll 8
        for (int t = 0; t < NT; t++) {
            float vv = v1 + zs[t * 64 + tid];
            float s  = (vv >= 1.0f) ? 1.0f : 0.0f;
            vv = (s != 0.f) ? 0.f : vv;
            v1 = fmaxf(vv, -1.0f);
            ss[t * 64 + tid] = s;
        }
    }
    __syncthreads();

    // Phase 2: z2[t][o] = ss[t][:] . w4[o][:]
    for (int i = tid; i < NT * 11; i += 256) {
        int t = i / 11, o = i - 11 * t;
        const float* sp = &ss[t * 64];
        const float* wp = &w4s[o * 65];
        float za = 0.f, zb = 0.f, zc = 0.f, zd = 0.f;
#pragma unroll
        for (int j = 0; j < 64; j += 4) {
            za = fmaf(sp[j],     wp[j],     za);
            zb = fmaf(sp[j + 1], wp[j + 1], zb);
            zc = fmaf(sp[j + 2], wp[j + 2], zc);
            zd = fmaf(sp[j + 3], wp[j + 3], zd);
        }
        z2[i] = (za + zb) + (zc + zd);
    }
    __syncthreads();

    // Phase 3: per-output IAF scan, barrier-free
    if (tid < 11) {
        float v2 = 0.f;
#pragma unroll 8
        for (int t = 0; t < NT; t++) {
            float vv2 = v2 + z2[t * 11 + tid];
            float s2  = (vv2 >= 1.0f) ? 1.0f : 0.0f;
            vv2 = (s2 != 0.f) ? 0.f : vv2;
            v2 = fmaxf(vv2, -1.0f);
            out[(b * NT + t) * 11 + tid] = s2;
        }
    }
}

// ---------------------------------------------------------------------------
extern "C" void kernel_launch(void* const* d_in, const int* in_sizes, int n_in,
                              void* d_out, int out_size) {
    (void)in_sizes; (void)n_in; (void)out_size;
    const float* x  = (const float*)d_in[0];
    const float* w1 = (const float*)d_in[1];
    const float* w2 = (const float*)d_in[2];
    const float* w3 = (const float*)d_in[3];
    const float* w4 = (const float*)d_in[4];
    float* out = (float*)d_out;

    kA<<<dim3(16, 25), 256>>>(x, w1);
    kB<<<dim3(4, 2, 25), 128>>>(w2);
    kC1<<<dim3(32, 4), 256>>>(w3);
    kC2<<<25, 256>>>(w4, out);
}